// round 2
// baseline (speedup 1.0000x reference)
#include <cuda_runtime.h>
#include <math.h>

typedef unsigned long long u64t;

// Packed f32x2 FMA (Blackwell full-rate fp32 path; 3-reg FFMA is half-rate on B300)
#define FMA2(d, a, b) asm("fma.rn.f32x2 %0, %1, %2, %0;" : "+l"(d) : "l"(a), "l"(b))
#define PACKF2(o, lo, hi) asm("mov.b64 %0, {%1, %2};" : "=l"(o) : "r"(__float_as_uint(lo)), "r"(__float_as_uint(hi)))

// Scratch (allocation-free rule: __device__ globals)
__device__ float g_s1[4096 * 32 * 196];   // pooled conv1 output (N,32,14,14)
__device__ float g_s2[4096 * 64 * 49];    // pooled conv2 output (N,64,7,7)
__device__ float g_fc1[4096 * 128];       // fc1 output (post relu)

// ---------------------------------------------------------------------------
// k1: gabor-bank conv (16 ch) + identity ch (16) + relu + maxpool2 -> g_s1
// One block per image. Gabor weights recomputed per block (144 exp/cos, trivial).
// ---------------------------------------------------------------------------
__global__ void __launch_bounds__(256) pcf_k1(
    const float* __restrict__ x, const float* __restrict__ theta,
    const float* __restrict__ sigma, const float* __restrict__ gamma_,
    const float* __restrict__ lambd, const float* __restrict__ psi)
{
    __shared__ float ps[30][30];   // zero-padded 28x28 input
    __shared__ float gw[16][9];    // gabor filters
    const int n = blockIdx.x, t = threadIdx.x;

    for (int idx = t; idx < 900; idx += 256) ((float*)ps)[idx] = 0.f;
    __syncthreads();

    const float* xim = x + (size_t)n * 784;
    for (int idx = t; idx < 784; idx += 256) {
        int r = idx / 28, c = idx - r * 28;
        ps[r + 1][c + 1] = xim[idx];
    }
    if (t < 144) {
        int f = t / 9, k = t - f * 9;
        float xg = (float)(k / 3) - 1.f;   // meshgrid 'ij': row offset
        float yg = (float)(k % 3) - 1.f;   // col offset
        float th = theta[f];
        float cth = cosf(th), sth = sinf(th);
        float xt = xg * cth + yg * sth;
        float yt = -xg * sth + yg * cth;
        float sx = sigma[f];
        float sy = sigma[f] / gamma_[f];
        float env = expf(-0.5f * (xt * xt / (sx * sx) + yt * yt / (sy * sy)));
        float car = cosf(6.283185307179586f * xt / lambd[f] + psi[f]);
        gw[f][k] = env * car;
    }
    __syncthreads();

    float* out1 = g_s1 + (size_t)n * 6272;

    // identity channels 16..31: all identical = maxpool(relu(x))
    if (t < 196) {
        int i = t / 14, j = t - (t / 14) * 14;
        float m = fmaxf(fmaxf(ps[2 * i + 1][2 * j + 1], ps[2 * i + 1][2 * j + 2]),
                        fmaxf(ps[2 * i + 2][2 * j + 1], ps[2 * i + 2][2 * j + 2]));
        m = fmaxf(m, 0.f);
#pragma unroll
        for (int c = 16; c < 32; c++) out1[c * 196 + t] = m;
    }

    // gabor channels: conv 3x3 (pad 1) + relu + maxpool2
    for (int idx = t; idx < 16 * 196; idx += 256) {
        int c = idx / 196, p = idx - (idx / 196) * 196;
        int i = p / 14, j = p - (p / 14) * 14;
        float w[9];
#pragma unroll
        for (int k = 0; k < 9; k++) w[k] = gw[c][k];
        float m = -1e30f;
#pragma unroll
        for (int di = 0; di < 2; di++)
#pragma unroll
            for (int dj = 0; dj < 2; dj++) {
                float s = 0.f;
#pragma unroll
                for (int kh = 0; kh < 3; kh++)
#pragma unroll
                    for (int kw = 0; kw < 3; kw++)
                        s += ps[2 * i + di + kh][2 * j + dj + kw] * w[kh * 3 + kw];
                m = fmaxf(m, s);
            }
        out1[c * 196 + p] = fmaxf(m, 0.f);
    }
}

// ---------------------------------------------------------------------------
// k2: conv2 (64x32x3x3, pad 1) + bias + relu + maxpool2 -> g_s2
// One block per image, 448 threads = 14 warps.
// warp -> pooled row i = warp>>1 ; lane+warp parity -> output channel o (0..63)
// f32x2 accumulators: lanes = pool-column pairs (2j, 2j+1).
// ---------------------------------------------------------------------------
__global__ void __launch_bounds__(448, 1) pcf_k2(
    const float* __restrict__ w2g, const float* __restrict__ b2)
{
    extern __shared__ float sm[];
    float* si = sm;            // 32 ch x 16 x 16 padded input = 8192 floats
    float* ws = sm + 8192;     // weights, per-o stride 289 (odd -> no bank conflict)
    const int n = blockIdx.x;
    const int t = threadIdx.x;

    for (int idx = t; idx < 8192; idx += 448) si[idx] = 0.f;
    for (int idx = t; idx < 64 * 288; idx += 448) {
        int o = idx / 288;
        ws[o * 289 + (idx - o * 288)] = w2g[idx];
    }
    __syncthreads();

    const float* in = g_s1 + (size_t)n * 6272;
    for (int idx = t; idx < 6272; idx += 448) {
        int ci = idx / 196;
        int p = idx - ci * 196;
        int r = p / 14, c = p - r * 14;
        si[ci * 256 + (r + 1) * 16 + (c + 1)] = in[idx];
    }
    __syncthreads();

    const int warp = t >> 5, lane = t & 31;
    const int i = warp >> 1;                    // pooled row 0..6
    const int o = ((warp & 1) << 5) | lane;     // output channel 0..63

    u64t acc2[2][7];
#pragma unroll
    for (int lr = 0; lr < 2; lr++)
#pragma unroll
        for (int j = 0; j < 7; j++) acc2[lr][j] = 0ull;

    const float* wsbase = ws + o * 289;
    const float* rowbase = si + 2 * i * 16;

#pragma unroll 1
    for (int ci = 0; ci < 32; ci++) {
        u64t wp[9];
#pragma unroll
        for (int k = 0; k < 9; k++) {
            float w = wsbase[ci * 9 + k];
            PACKF2(wp[k], w, w);
        }
        const float* rb = rowbase + ci * 256;
#pragma unroll
        for (int r = 0; r < 4; r++) {
            float rv[16];
            const float4* rp = (const float4*)(rb + r * 16);
#pragma unroll
            for (int q = 0; q < 4; q++) {
                float4 v = rp[q];
                rv[4 * q] = v.x; rv[4 * q + 1] = v.y; rv[4 * q + 2] = v.z; rv[4 * q + 3] = v.w;
            }
            u64t p0[8], p1[7];
#pragma unroll
            for (int q = 0; q < 8; q++) PACKF2(p0[q], rv[2 * q], rv[2 * q + 1]);
#pragma unroll
            for (int q = 0; q < 7; q++) PACKF2(p1[q], rv[2 * q + 1], rv[2 * q + 2]);
#pragma unroll
            for (int lr = 0; lr < 2; lr++) {
                const int kh = r - lr;         // compile-time after unroll
                if (kh >= 0 && kh < 3) {
                    u64t w0 = wp[kh * 3], w1 = wp[kh * 3 + 1], w2v = wp[kh * 3 + 2];
#pragma unroll
                    for (int j = 0; j < 7; j++) {
                        FMA2(acc2[lr][j], p0[j], w0);
                        FMA2(acc2[lr][j], p1[j], w1);
                        FMA2(acc2[lr][j], p0[j + 1], w2v);
                    }
                }
            }
        }
    }

    const float b = b2[o];
    float* outp = g_s2 + (size_t)n * 3136 + o * 49 + i * 7;
#pragma unroll
    for (int j = 0; j < 7; j++) {
        union { u64t u; float2 f; } a0, a1;
        a0.u = acc2[0][j];
        a1.u = acc2[1][j];
        float m = fmaxf(fmaxf(a0.f.x, a0.f.y), fmaxf(a1.f.x, a1.f.y));
        outp[j] = fmaxf(m + b, 0.f);   // relu(max(conv)+b) == max(relu(conv+b))
    }
}

// ---------------------------------------------------------------------------
// k3: fc1 = relu(A(4096x3136) @ W^T(3136x128) + b) -> g_fc1
// 64x64x32 tiles, 256 threads, micro 4x4 with f32x2. Transposed+XOR-swizzled
// smem tiles so frag loads are single float4 LDS.
// ---------------------------------------------------------------------------
__global__ void __launch_bounds__(256) pcf_k3(
    const float* __restrict__ w1, const float* __restrict__ b1)
{
    __shared__ float As[32 * 64];
    __shared__ float Bs[32 * 64];
    const int t = threadIdx.x;
    const int tx = t & 15, ty = t >> 4;
    const int n0 = blockIdx.x * 64;
    const int m0 = blockIdx.y * 64;

    u64t acc2[4][2];
#pragma unroll
    for (int u = 0; u < 4; u++) { acc2[u][0] = 0ull; acc2[u][1] = 0ull; }

    for (int kt = 0; kt < 98; kt++) {
#pragma unroll
        for (int s = 0; s < 8; s++) {
            int idx = t + s * 256;
            int k = idx & 31, row = idx >> 5;
            int phys = (((row >> 2) ^ (k & 15)) << 2) | (row & 3);
            As[k * 64 + phys] = g_s2[(size_t)(n0 + row) * 3136 + kt * 32 + k];
            Bs[k * 64 + phys] = w1[(size_t)(m0 + row) * 3136 + kt * 32 + k];
        }
        __syncthreads();
#pragma unroll
        for (int kk = 0; kk < 32; kk++) {
            float4 a4 = *(const float4*)(As + kk * 64 + ((ty ^ (kk & 15)) << 2));
            float4 b4 = *(const float4*)(Bs + kk * 64 + ((tx ^ (kk & 15)) << 2));
            u64t bp0, bp1;
            PACKF2(bp0, b4.x, b4.y);
            PACKF2(bp1, b4.z, b4.w);
            float av[4] = { a4.x, a4.y, a4.z, a4.w };
#pragma unroll
            for (int u = 0; u < 4; u++) {
                u64t ap;
                PACKF2(ap, av[u], av[u]);
                FMA2(acc2[u][0], bp0, ap);
                FMA2(acc2[u][1], bp1, ap);
            }
        }
        __syncthreads();
    }

#pragma unroll
    for (int u = 0; u < 4; u++) {
        int nrow = n0 + ty * 4 + u;
#pragma unroll
        for (int p = 0; p < 2; p++) {
            union { u64t v; float2 f; } cv;
            cv.v = acc2[u][p];
            int m = m0 + tx * 4 + p * 2;
            g_fc1[(size_t)nrow * 128 + m]     = fmaxf(cv.f.x + b1[m], 0.f);
            g_fc1[(size_t)nrow * 128 + m + 1] = fmaxf(cv.f.y + b1[m + 1], 0.f);
        }
    }
}

// ---------------------------------------------------------------------------
// k4: fc2 = g_fc1 @ W2^T + b2 -> out (4096x10). K=128, trivial.
// ---------------------------------------------------------------------------
__global__ void __launch_bounds__(256) pcf_k4(
    const float* __restrict__ w2, const float* __restrict__ b2,
    float* __restrict__ out)
{
    int gid = blockIdx.x * 256 + threadIdx.x;
    if (gid >= 4096 * 10) return;
    int nrow = gid / 10, o = gid - nrow * 10;
    const float4* a = (const float4*)(g_fc1 + (size_t)nrow * 128);
    const float4* w = (const float4*)(w2 + o * 128);
    float s = b2[o];
#pragma unroll
    for (int q = 0; q < 32; q++) {
        float4 av = a[q], wv = w[q];
        s += av.x * wv.x + av.y * wv.y + av.z * wv.z + av.w * wv.w;
    }
    out[gid] = s;
}

// ---------------------------------------------------------------------------
extern "C" void kernel_launch(void* const* d_in, const int* in_sizes, int n_in,
                              void* d_out, int out_size)
{
    const float* x       = (const float*)d_in[0];
    const float* theta   = (const float*)d_in[1];
    const float* sigma   = (const float*)d_in[2];
    const float* gamma_  = (const float*)d_in[3];
    const float* lambd   = (const float*)d_in[4];
    const float* psi     = (const float*)d_in[5];
    const float* conv2_w = (const float*)d_in[6];
    const float* conv2_b = (const float*)d_in[7];
    const float* fc1_w   = (const float*)d_in[8];
    const float* fc1_b   = (const float*)d_in[9];
    const float* fc2_w   = (const float*)d_in[10];
    const float* fc2_b   = (const float*)d_in[11];
    float* out = (float*)d_out;

    const int k2_smem = (8192 + 64 * 289) * 4;   // 106752 bytes
    cudaFuncSetAttribute(pcf_k2, cudaFuncAttributeMaxDynamicSharedMemorySize, k2_smem);

    pcf_k1<<<4096, 256>>>(x, theta, sigma, gamma_, lambd, psi);
    pcf_k2<<<4096, 448, k2_smem>>>(conv2_w, conv2_b);
    pcf_k3<<<dim3(64, 2), 256>>>(fc1_w, fc1_b);
    pcf_k4<<<160, 256>>>(fc2_w, fc2_b, out);
}

// round 3
// speedup vs baseline: 1.5504x; 1.5504x over previous
#include <cuda_runtime.h>
#include <math.h>

typedef unsigned long long u64t;

// Packed f32x2 FMA (Blackwell packed fp32 path)
#define FMA2(d, a, b) asm("fma.rn.f32x2 %0, %1, %2, %0;" : "+l"(d) : "l"(a), "l"(b))
#define PACKF2(o, lo, hi) asm("mov.b64 %0, {%1, %2};" : "=l"(o) : "r"(__float_as_uint(lo)), "r"(__float_as_uint(hi)))

// Scratch (allocation-free rule: __device__ globals)
__device__ float g_s1[4096 * 17 * 196];   // pooled conv1 output (N,17,14,14): 16 gabor + 1 shared identity
__device__ float g_s2[4096 * 64 * 49];    // pooled conv2 output (N,64,7,7)
__device__ float g_fc1[4096 * 128];       // fc1 output (post relu)
__device__ float g_w2eff[64 * 153];       // conv2 effective weights: [o][17*9] stride 153

// ---------------------------------------------------------------------------
// prep: fold the 16 identical identity channels of conv1 into ONE conv2
// input channel: w_eff[o][144+k] = sum_{ci=16..31} w2[o][ci][k]
// ---------------------------------------------------------------------------
__global__ void pcf_prep(const float* __restrict__ w2g)
{
    int idx = blockIdx.x * 256 + threadIdx.x;
    if (idx >= 64 * 153) return;
    int o = idx / 153, k = idx - o * 153;
    float v;
    if (k < 144) {
        v = w2g[o * 288 + k];                 // gabor ci 0..15 verbatim
    } else {
        int kk = k - 144;                     // 0..8
        v = 0.f;
#pragma unroll
        for (int ci = 16; ci < 32; ci++) v += w2g[o * 288 + ci * 9 + kk];
    }
    g_w2eff[o * 153 + k] = v;
}

// ---------------------------------------------------------------------------
// k1: gabor-bank conv (16 ch) + ONE identity ch + relu + maxpool2 -> g_s1
// One block per image. Gabor weights recomputed per block (trivial).
// ---------------------------------------------------------------------------
__global__ void __launch_bounds__(256) pcf_k1(
    const float* __restrict__ x, const float* __restrict__ theta,
    const float* __restrict__ sigma, const float* __restrict__ gamma_,
    const float* __restrict__ lambd, const float* __restrict__ psi)
{
    __shared__ float ps[30][30];   // zero-padded 28x28 input
    __shared__ float gw[16][9];    // gabor filters
    const int n = blockIdx.x, t = threadIdx.x;

    for (int idx = t; idx < 900; idx += 256) ((float*)ps)[idx] = 0.f;
    __syncthreads();

    const float* xim = x + (size_t)n * 784;
    for (int idx = t; idx < 784; idx += 256) {
        int r = idx / 28, c = idx - r * 28;
        ps[r + 1][c + 1] = xim[idx];
    }
    if (t < 144) {
        int f = t / 9, k = t - f * 9;
        float xg = (float)(k / 3) - 1.f;   // meshgrid 'ij': row offset
        float yg = (float)(k % 3) - 1.f;   // col offset
        float th = theta[f];
        float cth = cosf(th), sth = sinf(th);
        float xt = xg * cth + yg * sth;
        float yt = -xg * sth + yg * cth;
        float sx = sigma[f];
        float sy = sigma[f] / gamma_[f];
        float env = expf(-0.5f * (xt * xt / (sx * sx) + yt * yt / (sy * sy)));
        float car = cosf(6.283185307179586f * xt / lambd[f] + psi[f]);
        gw[f][k] = env * car;
    }
    __syncthreads();

    float* out1 = g_s1 + (size_t)n * 3332;   // 17*196

    // identity channel (shared by all 16 original maps): maxpool(relu(x))
    if (t < 196) {
        int i = t / 14, j = t - (t / 14) * 14;
        float m = fmaxf(fmaxf(ps[2 * i + 1][2 * j + 1], ps[2 * i + 1][2 * j + 2]),
                        fmaxf(ps[2 * i + 2][2 * j + 1], ps[2 * i + 2][2 * j + 2]));
        out1[16 * 196 + t] = fmaxf(m, 0.f);
    }

    // gabor channels: conv 3x3 (pad 1) + relu + maxpool2
    for (int idx = t; idx < 16 * 196; idx += 256) {
        int c = idx / 196, p = idx - (idx / 196) * 196;
        int i = p / 14, j = p - (p / 14) * 14;
        float w[9];
#pragma unroll
        for (int k = 0; k < 9; k++) w[k] = gw[c][k];
        float m = -1e30f;
#pragma unroll
        for (int di = 0; di < 2; di++)
#pragma unroll
            for (int dj = 0; dj < 2; dj++) {
                float s = 0.f;
#pragma unroll
                for (int kh = 0; kh < 3; kh++)
#pragma unroll
                    for (int kw = 0; kw < 3; kw++)
                        s += ps[2 * i + di + kh][2 * j + dj + kw] * w[kh * 3 + kw];
                m = fmaxf(m, s);
            }
        out1[c * 196 + p] = fmaxf(m, 0.f);
    }
}

// ---------------------------------------------------------------------------
// k2: conv2 over 17 effective channels + bias + relu + maxpool2 -> g_s2
// One block per image, 448 threads = 14 warps.
// warp -> pooled row i = warp>>1 ; lane+warp parity -> output channel o (0..63)
// f32x2 accumulators: lanes = pool-column pairs (2j, 2j+1).
// ---------------------------------------------------------------------------
__global__ void __launch_bounds__(448, 1) pcf_k2(const float* __restrict__ b2)
{
    extern __shared__ float sm[];
    float* si = sm;            // 17 ch x 16 x 16 padded input = 4352 floats
    float* ws = sm + 4352;     // weights, per-o stride 153 (odd -> no bank conflict)
    const int n = blockIdx.x;
    const int t = threadIdx.x;

    for (int idx = t; idx < 4352; idx += 448) si[idx] = 0.f;
    for (int idx = t; idx < 64 * 153; idx += 448) ws[idx] = g_w2eff[idx];
    __syncthreads();

    const float* in = g_s1 + (size_t)n * 3332;
    for (int idx = t; idx < 3332; idx += 448) {
        int ci = idx / 196;
        int p = idx - ci * 196;
        int r = p / 14, c = p - r * 14;
        si[ci * 256 + (r + 1) * 16 + (c + 1)] = in[idx];
    }
    __syncthreads();

    const int warp = t >> 5, lane = t & 31;
    const int i = warp >> 1;                    // pooled row 0..6
    const int o = ((warp & 1) << 5) | lane;     // output channel 0..63

    u64t acc2[2][7];
#pragma unroll
    for (int lr = 0; lr < 2; lr++)
#pragma unroll
        for (int j = 0; j < 7; j++) acc2[lr][j] = 0ull;

    const float* wsbase = ws + o * 153;
    const float* rowbase = si + 2 * i * 16;

#pragma unroll 1
    for (int ci = 0; ci < 17; ci++) {
        u64t wp[9];
#pragma unroll
        for (int k = 0; k < 9; k++) {
            float w = wsbase[ci * 9 + k];
            PACKF2(wp[k], w, w);
        }
        const float* rb = rowbase + ci * 256;
#pragma unroll
        for (int r = 0; r < 4; r++) {
            float rv[16];
            const float4* rp = (const float4*)(rb + r * 16);
#pragma unroll
            for (int q = 0; q < 4; q++) {
                float4 v = rp[q];
                rv[4 * q] = v.x; rv[4 * q + 1] = v.y; rv[4 * q + 2] = v.z; rv[4 * q + 3] = v.w;
            }
            u64t p0[8], p1[7];
#pragma unroll
            for (int q = 0; q < 8; q++) PACKF2(p0[q], rv[2 * q], rv[2 * q + 1]);
#pragma unroll
            for (int q = 0; q < 7; q++) PACKF2(p1[q], rv[2 * q + 1], rv[2 * q + 2]);
#pragma unroll
            for (int lr = 0; lr < 2; lr++) {
                const int kh = r - lr;         // compile-time after unroll
                if (kh >= 0 && kh < 3) {
                    u64t w0 = wp[kh * 3], w1 = wp[kh * 3 + 1], w2v = wp[kh * 3 + 2];
#pragma unroll
                    for (int j = 0; j < 7; j++) {
                        FMA2(acc2[lr][j], p0[j], w0);
                        FMA2(acc2[lr][j], p1[j], w1);
                        FMA2(acc2[lr][j], p0[j + 1], w2v);
                    }
                }
            }
        }
    }

    const float b = b2[o];
    float* outp = g_s2 + (size_t)n * 3136 + o * 49 + i * 7;
#pragma unroll
    for (int j = 0; j < 7; j++) {
        union { u64t u; float2 f; } a0, a1;
        a0.u = acc2[0][j];
        a1.u = acc2[1][j];
        float m = fmaxf(fmaxf(a0.f.x, a0.f.y), fmaxf(a1.f.x, a1.f.y));
        outp[j] = fmaxf(m + b, 0.f);   // relu(max(conv)+b) == max(relu(conv+b))
    }
}

// ---------------------------------------------------------------------------
// k3: fc1 = relu(A(4096x3136) @ W^T(3136x128) + b) -> g_fc1
// 64x64x32 tiles, 256 threads, micro 4x4 with f32x2. Transposed+XOR-swizzled
// smem tiles so frag loads are single float4 LDS.
// ---------------------------------------------------------------------------
__global__ void __launch_bounds__(256) pcf_k3(
    const float* __restrict__ w1, const float* __restrict__ b1)
{
    __shared__ float As[32 * 64];
    __shared__ float Bs[32 * 64];
    const int t = threadIdx.x;
    const int tx = t & 15, ty = t >> 4;
    const int n0 = blockIdx.x * 64;
    const int m0 = blockIdx.y * 64;

    u64t acc2[4][2];
#pragma unroll
    for (int u = 0; u < 4; u++) { acc2[u][0] = 0ull; acc2[u][1] = 0ull; }

    for (int kt = 0; kt < 98; kt++) {
#pragma unroll
        for (int s = 0; s < 8; s++) {
            int idx = t + s * 256;
            int k = idx & 31, row = idx >> 5;
            int phys = (((row >> 2) ^ (k & 15)) << 2) | (row & 3);
            As[k * 64 + phys] = g_s2[(size_t)(n0 + row) * 3136 + kt * 32 + k];
            Bs[k * 64 + phys] = w1[(size_t)(m0 + row) * 3136 + kt * 32 + k];
        }
        __syncthreads();
#pragma unroll
        for (int kk = 0; kk < 32; kk++) {
            float4 a4 = *(const float4*)(As + kk * 64 + ((ty ^ (kk & 15)) << 2));
            float4 b4 = *(const float4*)(Bs + kk * 64 + ((tx ^ (kk & 15)) << 2));
            u64t bp0, bp1;
            PACKF2(bp0, b4.x, b4.y);
            PACKF2(bp1, b4.z, b4.w);
            float av[4] = { a4.x, a4.y, a4.z, a4.w };
#pragma unroll
            for (int u = 0; u < 4; u++) {
                u64t ap;
                PACKF2(ap, av[u], av[u]);
                FMA2(acc2[u][0], bp0, ap);
                FMA2(acc2[u][1], bp1, ap);
            }
        }
        __syncthreads();
    }

#pragma unroll
    for (int u = 0; u < 4; u++) {
        int nrow = n0 + ty * 4 + u;
#pragma unroll
        for (int p = 0; p < 2; p++) {
            union { u64t v; float2 f; } cv;
            cv.v = acc2[u][p];
            int m = m0 + tx * 4 + p * 2;
            g_fc1[(size_t)nrow * 128 + m]     = fmaxf(cv.f.x + b1[m], 0.f);
            g_fc1[(size_t)nrow * 128 + m + 1] = fmaxf(cv.f.y + b1[m + 1], 0.f);
        }
    }
}

// ---------------------------------------------------------------------------
// k4: fc2 = g_fc1 @ W2^T + b2 -> out (4096x10). K=128, trivial.
// ---------------------------------------------------------------------------
__global__ void __launch_bounds__(256) pcf_k4(
    const float* __restrict__ w2, const float* __restrict__ b2,
    float* __restrict__ out)
{
    int gid = blockIdx.x * 256 + threadIdx.x;
    if (gid >= 4096 * 10) return;
    int nrow = gid / 10, o = gid - nrow * 10;
    const float4* a = (const float4*)(g_fc1 + (size_t)nrow * 128);
    const float4* w = (const float4*)(w2 + o * 128);
    float s = b2[o];
#pragma unroll
    for (int q = 0; q < 32; q++) {
        float4 av = a[q], wv = w[q];
        s += av.x * wv.x + av.y * wv.y + av.z * wv.z + av.w * wv.w;
    }
    out[gid] = s;
}

// ---------------------------------------------------------------------------
extern "C" void kernel_launch(void* const* d_in, const int* in_sizes, int n_in,
                              void* d_out, int out_size)
{
    const float* x       = (const float*)d_in[0];
    const float* theta   = (const float*)d_in[1];
    const float* sigma   = (const float*)d_in[2];
    const float* gamma_  = (const float*)d_in[3];
    const float* lambd   = (const float*)d_in[4];
    const float* psi     = (const float*)d_in[5];
    const float* conv2_w = (const float*)d_in[6];
    const float* conv2_b = (const float*)d_in[7];
    const float* fc1_w   = (const float*)d_in[8];
    const float* fc1_b   = (const float*)d_in[9];
    const float* fc2_w   = (const float*)d_in[10];
    const float* fc2_b   = (const float*)d_in[11];
    float* out = (float*)d_out;

    const int k2_smem = (4352 + 64 * 153) * 4;   // 56576 bytes
    cudaFuncSetAttribute(pcf_k2, cudaFuncAttributeMaxDynamicSharedMemorySize, k2_smem);

    pcf_prep<<<(64 * 153 + 255) / 256, 256>>>(conv2_w);
    pcf_k1<<<4096, 256>>>(x, theta, sigma, gamma_, lambd, psi);
    pcf_k2<<<4096, 448, k2_smem>>>(conv2_b);
    pcf_k3<<<dim3(64, 2), 256>>>(fc1_w, fc1_b);
    pcf_k4<<<160, 256>>>(fc2_w, fc2_b, out);
}